// round 14
// baseline (speedup 1.0000x reference)
#include <cuda_runtime.h>

// out[m,o] = sum_c |x[m,c] - w[c,o]| + b[o]
// rt-weighted pipe balance: channels 0..47 via max-trick (FMNMX alu@rt2 +
// FFMA-imm fma@rt1), channels 48..63 via |x-w| (FFMA-imm diff with pre-negated
// w + FADD-abs accumulate). fma-pipe floor drops 31K -> ~16K cyc/SM.
// Frame = R13 (best measured): BM=32, grid 784, dist-2 pipelined LDS operands.

constexpr int C    = 64;
constexpr int CP   = 32;    // channels per staging pass
constexpr int OUTC = 128;
constexpr int BM   = 32;
constexpr int XS   = 36;    // padded stride for transposed x tile

// acc = t*1.0(imm) + acc  -> FFMA-imm form, rt_SMSP=1 (2x FADD throughput)
__device__ __forceinline__ void ffma1(float& acc, float t) {
    asm("fma.rn.f32 %0, %1, 0f3F800000, %0;" : "+f"(acc) : "f"(t));
}
// d = x*1.0(imm) + wneg   (== x - w exactly, FFMA-imm)
__device__ __forceinline__ float ffma1d(float xv, float wneg) {
    float d;
    asm("fma.rn.f32 %0, %1, 0f3F800000, %2;" : "=f"(d) : "f"(xv), "f"(wneg));
    return d;
}

__global__ __launch_bounds__(256)
void lp1_maxtrick_kernel(const float* __restrict__ x,
                         const float* __restrict__ w,
                         const float* __restrict__ b,
                         float* __restrict__ out)
{
    __shared__ float w_s[CP * OUTC];  // 16 KB per pass (pass1: c>=16 stored negated)
    __shared__ float x_s[CP * XS];    // 4.6 KB per pass
    __shared__ float sx_s[BM];
    __shared__ float beta_s[OUTC];

    const int tid   = threadIdx.x;
    const int m_blk = blockIdx.x * BM;

    const int o0 = (tid & 31) * 4;    // 16B lane stride (conflict-free)
    const int m0 = (tid >> 5) * 4;    // warp-uniform -> broadcast x LDS.128

    float accm[4][4];                 // max-trick sums (channels 0..47)
    float accf[4][4];                 // |diff| sums   (channels 48..63)
    #pragma unroll
    for (int i = 0; i < 4; ++i)
        #pragma unroll
        for (int j = 0; j < 4; ++j) { accm[i][j] = 0.f; accf[i][j] = 0.f; }

    float beta_acc = (tid < OUTC) ? b[tid] : 0.f;   // b[o] - Sw[o] (max channels only)
    float sx_acc   = 0.f;                           // Sx[m]        (max channels only)

    #pragma unroll
    for (int pass = 0; pass < 2; ++pass) {
        const int cbase = pass * CP;

        // ---- stage w half [CP][OUTC]; pass1 local c>=16 stored NEGATED ----
        #pragma unroll
        for (int i = 0; i < 4; ++i) {
            int idx = tid + 256 * i;
            int c   = idx >> 5;
            int o4  = idx & 31;
            float4 v = *(const float4*)(w + (cbase + c) * OUTC + o4 * 4);
            if (pass == 1 && c >= 16) { v.x = -v.x; v.y = -v.y; v.z = -v.z; v.w = -v.w; }
            *(float4*)(&w_s[c * OUTC + o4 * 4]) = v;
        }
        // ---- stage x half transposed ----
        {
            int m = tid >> 3;
            int c = (tid & 7) << 2;
            float4 v = *(const float4*)(x + (size_t)(m_blk + m) * C + cbase + c);
            x_s[(c + 0) * XS + m] = v.x;
            x_s[(c + 1) * XS + m] = v.y;
            x_s[(c + 2) * XS + m] = v.z;
            x_s[(c + 3) * XS + m] = v.w;
        }
        __syncthreads();

        // ---- corrections: max-trick channels only (pass0 all, pass1 c<16) ----
        const int ccorr = (pass == 0) ? CP : 16;
        if (tid < OUTC) {
            for (int c = 0; c < ccorr; ++c) beta_acc -= w_s[c * OUTC + tid];
        } else if (tid < OUTC + BM) {
            int m = tid - OUTC;
            for (int c = 0; c < ccorr; ++c) sx_acc += x_s[c * XS + m];
        }

        // ---- main loop: distance-2 pipelined operands ----
        float4 xb[2], wb[2];
        xb[0] = *(const float4*)(&x_s[m0]);
        wb[0] = *(const float4*)(&w_s[o0]);
        xb[1] = *(const float4*)(&x_s[XS + m0]);
        wb[1] = *(const float4*)(&w_s[OUTC + o0]);
        #pragma unroll
        for (int c = 0; c < CP; ++c) {
            float4 xn = xb[c & 1], wn = wb[c & 1];
            if (c + 2 < CP) {
                xb[c & 1] = *(const float4*)(&x_s[(c + 2) * XS + m0]);
                wb[c & 1] = *(const float4*)(&w_s[(c + 2) * OUTC + o0]);
            }
            float xa[4] = {xn.x, xn.y, xn.z, xn.w};
            float wa[4] = {wn.x, wn.y, wn.z, wn.w};
            if (pass == 0 || c < 16) {
                // max-trick: FMNMX (alu) + FFMA-imm (fma, rt1)
                #pragma unroll
                for (int i = 0; i < 4; ++i)
                    #pragma unroll
                    for (int j = 0; j < 4; ++j)
                        ffma1(accm[i][j], fmaxf(xa[i], wa[j]));
            } else {
                // abs path: wa holds -w. d = x + (-w) via FFMA-imm; acc += |d| (FADD)
                #pragma unroll
                for (int i = 0; i < 4; ++i)
                    #pragma unroll
                    for (int j = 0; j < 4; ++j)
                        accf[i][j] += fabsf(ffma1d(xa[i], wa[j]));
            }
        }
        __syncthreads();
    }

    // ---- publish corrections ----
    if (tid < OUTC)            beta_s[tid]      = beta_acc;
    else if (tid < OUTC + BM)  sx_s[tid - OUTC] = sx_acc;
    __syncthreads();

    // ---- epilogue: out = 2*Smax + Sabs - sx + beta ----
    float bet[4];
    #pragma unroll
    for (int j = 0; j < 4; ++j) bet[j] = beta_s[o0 + j];

    #pragma unroll
    for (int i = 0; i < 4; ++i) {
        float base = -sx_s[m0 + i];
        float4 r;
        r.x = fmaf(2.f, accm[i][0], accf[i][0] + base + bet[0]);
        r.y = fmaf(2.f, accm[i][1], accf[i][1] + base + bet[1]);
        r.z = fmaf(2.f, accm[i][2], accf[i][2] + base + bet[2]);
        r.w = fmaf(2.f, accm[i][3], accf[i][3] + base + bet[3]);
        *(float4*)(out + (size_t)(m_blk + m0 + i) * OUTC + o0) = r;
    }
}

extern "C" void kernel_launch(void* const* d_in, const int* in_sizes, int n_in,
                              void* d_out, int out_size)
{
    const float* x = (const float*)d_in[0];   // [M, 64]
    const float* w = (const float*)d_in[1];   // [64, 128]
    const float* b = (const float*)d_in[2];   // [128]
    float* out = (float*)d_out;               // [M, 128]

    int M = in_sizes[0] / C;                  // 25088
    dim3 grid(M / BM, 1);                     // (784, 1)
    lp1_maxtrick_kernel<<<grid, 256>>>(x, w, b, out);
}

// round 15
// speedup vs baseline: 1.0747x; 1.0747x over previous
#include <cuda_runtime.h>
#include <cuda_fp16.h>

// out[m,o] = sum_c |x[m,c] - w[c,o]| + b[o]
// f16x2 o-pair packed inner loop: HSUB2 + HADD2(|src|) = 2 insts per 2 MACs
// (1 inst/MAC, half the fp32 slot count). Packed partials promoted to fp32
// every 8 channels (keeps accumulation error ~2e-4 L2). No corrections needed.

constexpr int C    = 64;
constexpr int OUTC = 128;
constexpr int BM   = 32;
constexpr int XP   = 36;    // x2 row stride in half2 (32 + 4 pad, 16B-aligned rows)

union W2 { float2 f; __half2 h[2]; };
union X4 { float4 f; __half2 h[4]; };

__global__ __launch_bounds__(256)
void lp1_h2_kernel(const float* __restrict__ x,
                   const float* __restrict__ w,
                   const float* __restrict__ b,
                   float* __restrict__ out)
{
    __shared__ __half2 w2_s[C * 64];   // [c][o/2]  o-pairs, 16 KB
    __shared__ __half2 x2_s[C * XP];   // [c][m]    duplicated (x,x), 9.2 KB

    const int tid   = threadIdx.x;
    const int m_blk = blockIdx.x * BM;

    // ---- stage w -> half2 o-pairs: 2048 float4, 8 per thread (coalesced) ----
    #pragma unroll
    for (int i = 0; i < 8; ++i) {
        int idx = tid + 256 * i;              // 0..2047
        int c   = idx >> 5;                   // 32 float4 per c-row
        int o4  = idx & 31;
        float4 v = *(const float4*)(w + c * OUTC + o4 * 4);
        w2_s[c * 64 + o4 * 2 + 0] = __floats2half2_rn(v.x, v.y);
        w2_s[c * 64 + o4 * 2 + 1] = __floats2half2_rn(v.z, v.w);
    }

    // ---- stage x -> duplicated half2, transposed: 512 float4, 2 per thread ----
    #pragma unroll
    for (int i = 0; i < 2; ++i) {
        int idx = tid + 256 * i;              // 0..511
        int m   = idx >> 4;                   // 16 float4 per row (C=64)
        int c   = (idx & 15) << 2;
        float4 v = *(const float4*)(x + (size_t)(m_blk + m) * C + c);
        x2_s[(c + 0) * XP + m] = __half2half2(__float2half_rn(v.x));
        x2_s[(c + 1) * XP + m] = __half2half2(__float2half_rn(v.y));
        x2_s[(c + 2) * XP + m] = __half2half2(__float2half_rn(v.z));
        x2_s[(c + 3) * XP + m] = __half2half2(__float2half_rn(v.w));
    }
    __syncthreads();

    const int o0 = (tid & 31) * 4;    // 32 o-groups over 128
    const int m0 = (tid >> 5) * 4;    // 8 m-groups over 32 (warp-uniform)

    float accf[4][4];
    #pragma unroll
    for (int i = 0; i < 4; ++i)
        #pragma unroll
        for (int j = 0; j < 4; ++j) accf[i][j] = 0.f;

    const __half2* xp = &x2_s[m0];                    // broadcast LDS.128 (4 half2)
    const __half2* wp = &w2_s[(tid & 31) * 2];        // 8B lane stride (2 half2)

    // ---- hot loop: 8 groups x 8 channels; f16x2 accumulate, fp32 promote ----
    for (int g = 0; g < 8; ++g) {
        __half2 acc2[4][2];
        #pragma unroll
        for (int i = 0; i < 4; ++i) {
            acc2[i][0] = __float2half2_rn(0.f);
            acc2[i][1] = __float2half2_rn(0.f);
        }

        #pragma unroll
        for (int cc = 0; cc < 8; ++cc) {
            int c = g * 8 + cc;
            X4 xu; xu.f = *(const float4*)(xp + c * XP);   // (x0,x0)..(x3,x3)
            W2 wu; wu.f = *(const float2*)(wp + c * 64);   // (w0,w1),(w2,w3)
            #pragma unroll
            for (int i = 0; i < 4; ++i) {
                acc2[i][0] = __hadd2(acc2[i][0], __habs2(__hsub2(xu.h[i], wu.h[0])));
                acc2[i][1] = __hadd2(acc2[i][1], __habs2(__hsub2(xu.h[i], wu.h[1])));
            }
        }

        // promote packed partials (<=8 terms each) to fp32
        #pragma unroll
        for (int i = 0; i < 4; ++i) {
            float2 p0 = __half22float2(acc2[i][0]);
            float2 p1 = __half22float2(acc2[i][1]);
            accf[i][0] += p0.x;  accf[i][1] += p0.y;
            accf[i][2] += p1.x;  accf[i][3] += p1.y;
        }
    }

    // ---- epilogue: out = accf + b ----
    float4 bv = *(const float4*)(b + o0);
    #pragma unroll
    for (int i = 0; i < 4; ++i) {
        float4 r;
        r.x = accf[i][0] + bv.x;
        r.y = accf[i][1] + bv.y;
        r.z = accf[i][2] + bv.z;
        r.w = accf[i][3] + bv.w;
        *(float4*)(out + (size_t)(m_blk + m0 + i) * OUTC + o0) = r;
    }
}

extern "C" void kernel_launch(void* const* d_in, const int* in_sizes, int n_in,
                              void* d_out, int out_size)
{
    const float* x = (const float*)d_in[0];   // [M, 64]
    const float* w = (const float*)d_in[1];   // [64, 128]
    const float* b = (const float*)d_in[2];   // [128]
    float* out = (float*)d_out;               // [M, 128]

    int M = in_sizes[0] / C;                  // 25088
    dim3 grid(M / BM, 1);                     // (784, 1)
    lp1_h2_kernel<<<grid, 256>>>(x, w, b, out);
}

// round 17
// speedup vs baseline: 1.1220x; 1.0440x over previous
#include <cuda_runtime.h>
#include <cuda_fp16.h>

// out[m,o] = sum_c |x[m,c] - w[c,o]| + b[o]
// f16x2 packed math (HSUB2 + HADD2-with-|src| = 1 inst/MAC, R15-verified)
// + distance-2 software-pipelined LDS operands (R13-verified), fully unrolled.
// fp32 promotion every 8 channels (rel_err ~1.5e-4). Unions replaced by
// pointer bitcasts (zero-inst reinterpret) to fix the deleted-copy-ctor error.

constexpr int C    = 64;
constexpr int OUTC = 128;
constexpr int BM   = 32;
constexpr int XP   = 36;    // x2 row stride in half2 (32 + 4 pad)

__device__ __forceinline__ __half2 f2h2(float f) {   // bit reinterpret
    return *(const __half2*)&f;
}

__global__ __launch_bounds__(256)
void lp1_h2_kernel(const float* __restrict__ x,
                   const float* __restrict__ w,
                   const float* __restrict__ b,
                   float* __restrict__ out)
{
    __shared__ __half2 w2_s[C * 64];   // [c][o/2]  o-pairs, 16 KB
    __shared__ __half2 x2_s[C * XP];   // [c][m]    duplicated (x,x), 9.2 KB

    const int tid   = threadIdx.x;
    const int m_blk = blockIdx.x * BM;

    // ---- stage w -> half2 o-pairs: 2048 float4, 8 per thread (coalesced) ----
    #pragma unroll
    for (int i = 0; i < 8; ++i) {
        int idx = tid + 256 * i;              // 0..2047
        int c   = idx >> 5;                   // 32 float4 per c-row
        int o4  = idx & 31;
        float4 v = *(const float4*)(w + c * OUTC + o4 * 4);
        w2_s[c * 64 + o4 * 2 + 0] = __floats2half2_rn(v.x, v.y);
        w2_s[c * 64 + o4 * 2 + 1] = __floats2half2_rn(v.z, v.w);
    }

    // ---- stage x -> duplicated half2, transposed: 512 float4 ----
    #pragma unroll
    for (int i = 0; i < 2; ++i) {
        int idx = tid + 256 * i;              // 0..511
        int m   = idx >> 4;                   // 16 float4 per row (C=64)
        int c   = (idx & 15) << 2;
        float4 v = *(const float4*)(x + (size_t)(m_blk + m) * C + c);
        x2_s[(c + 0) * XP + m] = __half2half2(__float2half_rn(v.x));
        x2_s[(c + 1) * XP + m] = __half2half2(__float2half_rn(v.y));
        x2_s[(c + 2) * XP + m] = __half2half2(__float2half_rn(v.z));
        x2_s[(c + 3) * XP + m] = __half2half2(__float2half_rn(v.w));
    }
    __syncthreads();

    const int o0 = (tid & 31) * 4;    // 32 o-groups over 128
    const int m0 = (tid >> 5) * 4;    // 8 m-groups over 32 (warp-uniform)

    float accf[4][4];
    #pragma unroll
    for (int i = 0; i < 4; ++i)
        #pragma unroll
        for (int j = 0; j < 4; ++j) accf[i][j] = 0.f;

    const __half2* xp = &x2_s[m0];                 // broadcast LDS.128 per c
    const __half2* wp = &w2_s[(tid & 31) * 2];     // 8B-stride LDS.64 per c

    // ---- distance-2 pipelined, fully unrolled hot loop ----
    float4 xb[2]; float2 wb[2];
    xb[0] = *(const float4*)(xp);
    wb[0] = *(const float2*)(wp);
    xb[1] = *(const float4*)(xp + XP);
    wb[1] = *(const float2*)(wp + 64);

    __half2 acc2[4][2];
    #pragma unroll
    for (int i = 0; i < 4; ++i) {
        acc2[i][0] = __float2half2_rn(0.f);
        acc2[i][1] = __float2half2_rn(0.f);
    }

    #pragma unroll
    for (int c = 0; c < C; ++c) {
        float4 xu = xb[c & 1];
        float2 wu = wb[c & 1];
        if (c + 2 < C) {                           // compile-time guard
            xb[c & 1] = *(const float4*)(xp + (c + 2) * XP);
            wb[c & 1] = *(const float2*)(wp + (c + 2) * 64);
        }
        __half2 xh[4] = {f2h2(xu.x), f2h2(xu.y), f2h2(xu.z), f2h2(xu.w)};
        __half2 wh0 = f2h2(wu.x);
        __half2 wh1 = f2h2(wu.y);
        #pragma unroll
        for (int i = 0; i < 4; ++i) {
            acc2[i][0] = __hadd2(acc2[i][0], __habs2(__hsub2(xh[i], wh0)));
            acc2[i][1] = __hadd2(acc2[i][1], __habs2(__hsub2(xh[i], wh1)));
        }
        if ((c & 7) == 7) {                        // promote every 8 channels
            #pragma unroll
            for (int i = 0; i < 4; ++i) {
                float2 p0 = __half22float2(acc2[i][0]);
                float2 p1 = __half22float2(acc2[i][1]);
                accf[i][0] += p0.x;  accf[i][1] += p0.y;
                accf[i][2] += p1.x;  accf[i][3] += p1.y;
                acc2[i][0] = __float2half2_rn(0.f);
                acc2[i][1] = __float2half2_rn(0.f);
            }
        }
    }

    // ---- epilogue: out = accf + b ----
    float4 bv = *(const float4*)(b + o0);
    #pragma unroll
    for (int i = 0; i < 4; ++i) {
        float4 r;
        r.x = accf[i][0] + bv.x;
        r.y = accf[i][1] + bv.y;
        r.z = accf[i][2] + bv.z;
        r.w = accf[i][3] + bv.w;
        *(float4*)(out + (size_t)(m_blk + m0 + i) * OUTC + o0) = r;
    }
}

extern "C" void kernel_launch(void* const* d_in, const int* in_sizes, int n_in,
                              void* d_out, int out_size)
{
    const float* x = (const float*)d_in[0];   // [M, 64]
    const float* w = (const float*)d_in[1];   // [64, 128]
    const float* b = (const float*)d_in[2];   // [128]
    float* out = (float*)d_out;               // [M, 128]

    int M = in_sizes[0] / C;                  // 25088
    dim3 grid(M / BM, 1);                     // (784, 1)
    lp1_h2_kernel<<<grid, 256>>>(x, w, b, out);
}